// round 9
// baseline (speedup 1.0000x reference)
#include <cuda_runtime.h>
#include <cuda_bf16.h>
#include <cstdint>
#include <math.h>

// Problem constants (fixed by the dataset's setup_inputs)
#define B_    256
#define NIN_  1024
#define NOUT_ 256
#define NH_   2048
#define L_    4
#define T_    32

// ================= scratch (static __device__ — no allocation) =================
__device__ __align__(128) signed char g_wb1[L_][NH_][NH_];  // W_rec int8 hi [l][n][k] 16MB
__device__ __align__(128) signed char g_wb2[L_][NH_][NH_];  // W_rec int8 lo           16MB
__device__ __align__(128) signed char g_ha1[2][L_][B_][NH_];// h int8 hi [m][k]         4MB
__device__ __align__(128) signed char g_ha2[2][L_][B_][NH_];// h int8 lo                4MB
__device__ float g_G[L_][B_][NH_];        // recurrent GEMM out [l][m][n]   8 MB
__device__ float g_xin_mn[B_][NH_];       // x_in [m][n]                    2 MB
__device__ float g_hTmn[B_][NH_];         // layer L-1 fp32 h [m][n]        2 MB
__device__ float g_hnm[NH_][B_];          // transposed for out proj        2 MB
__device__ float g_Win_T[NIN_][NH_];      // W_in transposed [k][n]         8 MB
__device__ float g_X_T[NIN_][B_];         // X transposed [k][m]            1 MB
__device__ float g_Wout_T[NH_][NOUT_];    // W_out transposed [k][n]        2 MB
__device__ float g_xin[NH_][B_];          // x_in [n][m] (fp32 gemm output) 2 MB
__device__ float g_ppart[4][NH_][B_];     // proj split-K partials          8 MB
__device__ float g_opart[32][NOUT_][B_];  // out  split-K partials          8 MB

// quantization constants: s = 1/sqrt(2048) (exact uniform bound of W_rec)
#define WS_   (127.0f * 45.25483399593904f)          // 127/s
#define C1_   (0.022097086912079612f / 16129.0f)     // s/(127*127)

// ================= PTX helpers =================
__device__ __forceinline__ unsigned long long fdup(float a) {
    unsigned long long r; unsigned ai = __float_as_uint(a);
    asm("mov.b64 %0, {%1, %1};" : "=l"(r) : "r"(ai));
    return r;
}
__device__ __forceinline__ void fma2(unsigned long long& d, unsigned long long a,
                                     unsigned long long b) {
    asm("fma.rn.f32x2 %0, %1, %2, %0;" : "+l"(d) : "l"(a), "l"(b));
}
__device__ __forceinline__ void cpa16(void* sdst, const void* gsrc) {
    unsigned saddr = (unsigned)__cvta_generic_to_shared(sdst);
    asm volatile("cp.async.cg.shared.global [%0], [%1], 16;\n" :: "r"(saddr), "l"(gsrc));
}
__device__ __forceinline__ void cpa16s(unsigned saddr, const void* gsrc) {
    asm volatile("cp.async.cg.shared.global [%0], [%1], 16;\n" :: "r"(saddr), "l"(gsrc));
}
__device__ __forceinline__ void cpa_commit() { asm volatile("cp.async.commit_group;\n"); }
template <int N_> __device__ __forceinline__ void cpa_wait() {
    asm volatile("cp.async.wait_group %0;\n" :: "n"(N_));
}
__device__ __forceinline__ uint32_t smem_u32(const void* p) {
    uint32_t a;
    asm("{ .reg .u64 t; cvta.to.shared.u64 t, %1; cvt.u32.u64 %0, t; }" : "=r"(a) : "l"(p));
    return a;
}
__device__ __forceinline__ void ldm_x4(uint32_t& r0, uint32_t& r1, uint32_t& r2,
                                       uint32_t& r3, uint32_t addr) {
    asm volatile("ldmatrix.sync.aligned.m8n8.x4.shared.b16 {%0,%1,%2,%3}, [%4];"
                 : "=r"(r0), "=r"(r1), "=r"(r2), "=r"(r3) : "r"(addr));
}
__device__ __forceinline__ void mma_s8(int* c, const uint32_t* a, uint32_t b0,
                                       uint32_t b1) {
    asm volatile(
        "mma.sync.aligned.m16n8k32.row.col.s32.s8.s8.s32 "
        "{%0,%1,%2,%3}, {%4,%5,%6,%7}, {%8,%9}, {%0,%1,%2,%3};"
        : "+r"(c[0]), "+r"(c[1]), "+r"(c[2]), "+r"(c[3])
        : "r"(a[0]), "r"(a[1]), "r"(a[2]), "r"(a[3]), "r"(b0), "r"(b1));
}

// ================= IMMA recurrent GEMM =================
// G[l][m][n] = sum_k h[m][k]*W[l][n][k]; h=(a1+a2/254)/127, w=(b1+b2/254)*s/127.
// 3 int8 passes: P1=a1*b1 -> acc1;  P2=a2*b1, P3=a1*b2 -> acc2 (both exact s32).
// G = C1*acc1 + (C1/254)*acc2.
// CTA tile 128x128, BK=64 (2 k32 sub-iters), 8 warps (64x32), double buffer.
// Smem rows 64B (4 x 16B chunks), swizzle phys_chunk = c ^ ((row>>1)&3):
// ldmatrix 8-row fetches conflict-free (even rows banks 0-15, odd 16-31).
#define NS8 96       // 3 passes * (2048/64)
#define TIB 8192     // 128 rows * 64 B

__global__ void __launch_bounds__(256) k_mma_step(int pr) {
    __shared__ __align__(128) char smem[4 * TIB];  // A0 A1 B0 B1

    const int tid = threadIdx.x;
    const int wid = tid >> 5, lane = tid & 31;
    const int wm = wid & 1, wn = wid >> 1;
    const int m0 = blockIdx.x * 128;
    const int n0 = blockIdx.y * 128;
    const int l  = blockIdx.z;

    const uint32_t sbase = smem_u32(smem);

    const char* A1p = (const char*)&g_ha1[pr][l][m0][0];
    const char* A2p = (const char*)&g_ha2[pr][l][m0][0];
    const char* B1p = (const char*)&g_wb1[l][n0][0];
    const char* B2p = (const char*)&g_wb2[l][n0][0];

    auto load_stage = [&](int buf, int st) {
        const int p  = st >> 5;            // 0: a1*b1, 1: a2*b1, 2: a1*b2
        const int ko = (st & 31) * 64;     // byte offset along K
        const char* Asrc = (p == 1) ? A2p : A1p;
        const char* Bsrc = (p == 2) ? B2p : B1p;
        const uint32_t sA = sbase + buf * TIB;
        const uint32_t sB = sbase + 2 * TIB + buf * TIB;
#pragma unroll
        for (int ch = tid; ch < 512; ch += 256) {
            int row = ch >> 2, c = ch & 3;
            uint32_t sw = ((uint32_t)(c ^ ((row >> 1) & 3))) << 4;
            cpa16s(sA + row * 64 + sw, Asrc + (size_t)row * NH_ + ko + c * 16);
            cpa16s(sB + row * 64 + sw, Bsrc + (size_t)row * NH_ + ko + c * 16);
        }
        cpa_commit();
    };

    int acc1[4][4][4], acc2[4][4][4];
#pragma unroll
    for (int a = 0; a < 4; ++a)
#pragma unroll
        for (int b = 0; b < 4; ++b)
#pragma unroll
            for (int r = 0; r < 4; ++r) { acc1[a][b][r] = 0; acc2[a][b][r] = 0; }

    // per-lane ldmatrix addressing (swizzle component is lane-constant:
    // wm*64, mf*16, wn*32, nf2*16 all leave ((row>>1)&3) unchanged)
    const uint32_t swzA = ((lane & 15) >> 1) & 3;
    const uint32_t aRow = (uint32_t)(wm * 64 + (lane & 15));                     // + mf*16
    const uint32_t aHalf = (lane >> 4) & 1;
    const uint32_t bRow = (uint32_t)(wn * 32 + (lane & 7) + ((lane >> 4) << 3)); // + nf2*16
    const uint32_t swzB = (bRow >> 1) & 3;
    const uint32_t bHalf = (lane >> 3) & 1;

#define STEP_ITER(ACC) do {                                                   \
    const int b = i & 1;                                                      \
    if (i + 1 < NS8) { load_stage(b ^ 1, i + 1); cpa_wait<1>(); }             \
    else             { cpa_wait<0>(); }                                       \
    __syncthreads();                                                          \
    const uint32_t sA = sbase + b * TIB;                                      \
    const uint32_t sB = sbase + 2 * TIB + b * TIB;                            \
    _Pragma("unroll")                                                         \
    for (int ks = 0; ks < 2; ++ks) {                                          \
        uint32_t af[4][4];                                                    \
        _Pragma("unroll")                                                     \
        for (int mf = 0; mf < 4; ++mf) {                                      \
            uint32_t addr = sA + (aRow + mf * 16) * 64 +                      \
                            (((2 * ks + aHalf) ^ swzA) << 4);                 \
            ldm_x4(af[mf][0], af[mf][1], af[mf][2], af[mf][3], addr);         \
        }                                                                     \
        uint32_t bf[2][4];                                                    \
        _Pragma("unroll")                                                     \
        for (int nf2 = 0; nf2 < 2; ++nf2) {                                   \
            uint32_t addr = sB + (bRow + nf2 * 16) * 64 +                     \
                            (((2 * ks + bHalf) ^ swzB) << 4);                 \
            ldm_x4(bf[nf2][0], bf[nf2][1], bf[nf2][2], bf[nf2][3], addr);     \
        }                                                                     \
        _Pragma("unroll")                                                     \
        for (int mf = 0; mf < 4; ++mf)                                        \
            _Pragma("unroll")                                                 \
            for (int nf = 0; nf < 4; ++nf)                                    \
                mma_s8(ACC[mf][nf], af[mf], bf[nf >> 1][(nf & 1) * 2],        \
                       bf[nf >> 1][(nf & 1) * 2 + 1]);                        \
    }                                                                         \
    __syncthreads();                                                          \
} while (0)

    load_stage(0, 0);
    int i = 0;
    for (; i < 32; ++i)  STEP_ITER(acc1);   // pass 0 -> acc1
    for (; i < NS8; ++i) STEP_ITER(acc2);   // passes 1,2 -> acc2
#undef STEP_ITER

    // epilogue: c-frag m16n8 -> rows (lane>>2, +8), cols 2*(lane&3)
    const float C1f = C1_;
    const float C2f = C1_ * (1.0f / 254.0f);
    const int r = lane >> 2, cp = lane & 3;
#pragma unroll
    for (int mf = 0; mf < 4; ++mf)
#pragma unroll
        for (int nf = 0; nf < 4; ++nf) {
            float g0 = C1f * (float)acc1[mf][nf][0] + C2f * (float)acc2[mf][nf][0];
            float g1 = C1f * (float)acc1[mf][nf][1] + C2f * (float)acc2[mf][nf][1];
            float g2 = C1f * (float)acc1[mf][nf][2] + C2f * (float)acc2[mf][nf][2];
            float g3 = C1f * (float)acc1[mf][nf][3] + C2f * (float)acc2[mf][nf][3];
            float* dst = &g_G[l][m0 + wm * 64 + mf * 16 + r][n0 + wn * 32 + nf * 8 + cp * 2];
            *(float2*)dst = make_float2(g0, g1);
            *(float2*)(dst + 8 * NH_) = make_float2(g2, g3);
        }
}

// ================= weight split fp32 -> int8 hi/lo =================
__global__ void __launch_bounds__(256) k_split_W(const float* __restrict__ w) {
    size_t idx = (size_t)blockIdx.x * 256 + threadIdx.x;  // L*NH*NH threads
    float v = w[idx] * WS_;                                // |v| <= 127
    int b1 = __float2int_rn(v);
    float rres = v - (float)b1;                            // [-0.5, 0.5]
    int b2 = __float2int_rn(rres * 254.0f);
    ((signed char*)g_wb1)[idx] = (signed char)b1;
    ((signed char*)g_wb2)[idx] = (signed char)b2;
}

// ================= transpose (fp32 paths) =================
__device__ __forceinline__ void tr_body(const float* __restrict__ src,
                                        float* __restrict__ dst, int R, int C) {
    __shared__ float t[32][33];
    int c0 = blockIdx.x * 32, r0 = blockIdx.y * 32;
    int tx = threadIdx.x, ty = threadIdx.y;  // 32 x 8
#pragma unroll
    for (int i = 0; i < 32; i += 8)
        t[ty + i][tx] = src[(size_t)(r0 + ty + i) * C + c0 + tx];
    __syncthreads();
#pragma unroll
    for (int i = 0; i < 32; i += 8)
        dst[(size_t)(c0 + ty + i) * R + r0 + tx] = t[tx][ty + i];
}
__global__ void __launch_bounds__(256) k_tr_X(const float* __restrict__ s) {
    tr_body(s, &g_X_T[0][0], B_, NIN_);
}
__global__ void __launch_bounds__(256) k_tr_Win(const float* __restrict__ s) {
    tr_body(s, &g_Win_T[0][0], NH_, NIN_);
}
__global__ void __launch_bounds__(256) k_tr_Wout(const float* __restrict__ s) {
    tr_body(s, &g_Wout_T[0][0], NOUT_, NH_);
}
__global__ void __launch_bounds__(256) k_tr_xin() {    // [n][m] -> [m][n]
    tr_body(&g_xin[0][0], &g_xin_mn[0][0], NH_, B_);
}
__global__ void __launch_bounds__(256) k_tr_hfin() {   // [m][n] -> [n][m]
    tr_body(&g_hTmn[0][0], &g_hnm[0][0], B_, NH_);
}

// ================= fp32 SIMT GEMM (proj / out only) =================
#define BI 128
#define BJ 128
#define BK 16
__device__ __forceinline__ void gemm_tile(const float* __restrict__ A,
                                          const float* __restrict__ Bp,
                                          float* __restrict__ C,
                                          int lda, int ldb, int ldc,
                                          int k0, int klen) {
    __shared__ __align__(16) float As[2][BK][BI];
    __shared__ __align__(16) float Bs[2][BK][BJ];
    const int tid = threadIdx.x;
    const int tx = tid & 15;
    const int ty = tid >> 4;
    const int i0 = blockIdx.x * BI;
    const int j0 = blockIdx.y * BJ;
    const int lk = tid >> 5;
    const int li = (tid & 31) * 4;

#define LOAD_STAGE(buf, kbase)                                                        \
    do {                                                                              \
        cpa16(&As[buf][lk][li],     A  + (size_t)((kbase) + lk)     * lda + i0 + li); \
        cpa16(&As[buf][lk + 8][li], A  + (size_t)((kbase) + lk + 8) * lda + i0 + li); \
        cpa16(&Bs[buf][lk][li],     Bp + (size_t)((kbase) + lk)     * ldb + j0 + li); \
        cpa16(&Bs[buf][lk + 8][li], Bp + (size_t)((kbase) + lk + 8) * ldb + j0 + li); \
        cpa_commit();                                                                 \
    } while (0)

    unsigned long long acc[8][4];
#pragma unroll
    for (int ii = 0; ii < 8; ++ii)
#pragma unroll
        for (int jj = 0; jj < 4; ++jj) acc[ii][jj] = 0ull;

    const int nst = klen / BK;
    LOAD_STAGE(0, k0);
    for (int s = 0; s < nst; ++s) {
        const int cur = s & 1;
        if (s + 1 < nst) { LOAD_STAGE(cur ^ 1, k0 + (s + 1) * BK); cpa_wait<1>(); }
        else             { cpa_wait<0>(); }
        __syncthreads();
#pragma unroll
        for (int kk = 0; kk < BK; ++kk) {
            float4 alo = *(const float4*)&As[cur][kk][tx * 8];
            float4 ahi = *(const float4*)&As[cur][kk][tx * 8 + 4];
            ulonglong2 bA = *(const ulonglong2*)&Bs[cur][kk][ty * 8];
            ulonglong2 bB = *(const ulonglong2*)&Bs[cur][kk][ty * 8 + 4];
            unsigned long long bb0 = bA.x, bb1 = bA.y, bb2 = bB.x, bb3 = bB.y;
            float av[8] = {alo.x, alo.y, alo.z, alo.w, ahi.x, ahi.y, ahi.z, ahi.w};
#pragma unroll
            for (int ii = 0; ii < 8; ++ii) {
                unsigned long long ad = fdup(av[ii]);
                fma2(acc[ii][0], ad, bb0);
                fma2(acc[ii][1], ad, bb1);
                fma2(acc[ii][2], ad, bb2);
                fma2(acc[ii][3], ad, bb3);
            }
        }
        __syncthreads();
    }
#undef LOAD_STAGE
#pragma unroll
    for (int jj = 0; jj < 8; ++jj) {
        float v[8];
#pragma unroll
        for (int ii = 0; ii < 8; ++ii) {
            union { unsigned long long u; float2 f; } cv;
            cv.u = acc[ii][jj >> 1];
            v[ii] = (jj & 1) ? cv.f.y : cv.f.x;
        }
        float* row = C + (size_t)(j0 + ty * 8 + jj) * ldc + i0 + tx * 8;
        *(float4*)row       = make_float4(v[0], v[1], v[2], v[3]);
        *(float4*)(row + 4) = make_float4(v[4], v[5], v[6], v[7]);
    }
}
__global__ void __launch_bounds__(256) k_proj_gemm() {
    int z = blockIdx.z;
    gemm_tile(&g_X_T[0][0], &g_Win_T[0][0], &g_ppart[z][0][0], B_, NH_, B_,
              z * (NIN_ / 4), NIN_ / 4);
}
__global__ void __launch_bounds__(256) k_out_gemm() {
    int z = blockIdx.z;
    gemm_tile(&g_hnm[0][0], &g_Wout_T[0][0], &g_opart[z][0][0], B_, NOUT_, B_,
              z * (NH_ / 32), NH_ / 32);
}

// ================= elementwise =================
__global__ void __launch_bounds__(256) k_proj_reduce(const float* __restrict__ bin) {
    int idx = blockIdx.x * 256 + threadIdx.x;  // NH*B threads, [n][m]
    int n = idx >> 8, m = idx & (B_ - 1);
    float v = bin[n];
#pragma unroll
    for (int z = 0; z < 4; ++z) v += g_ppart[z][n][m];
    g_xin[n][m] = v;
}
__device__ __forceinline__ void store_q(int pw, int l, int m, int n, float v) {
    int q1 = __float2int_rn(v * 127.0f);             // |v| <= 1
    float rres = fmaf(v, 127.0f, -(float)q1);        // [-0.5, 0.5]
    int q2 = __float2int_rn(rres * 254.0f);
    g_ha1[pw][l][m][n] = (signed char)q1;
    g_ha2[pw][l][m][n] = (signed char)q2;
}
__global__ void __launch_bounds__(256) k_step0(const float* __restrict__ brec) {
    int idx = blockIdx.x * 256 + threadIdx.x;  // B*NH threads, [m][n]
    int m = idx >> 11, n = idx & (NH_ - 1);
    float v = sinf(g_xin_mn[m][n] + brec[n]);
    store_q(0, 0, m, n, v);
#pragma unroll
    for (int l = 1; l < L_; ++l) {
        v = sinf(v + brec[l * NH_ + n]);
        store_q(0, l, m, n, v);
    }
    g_hTmn[m][n] = v;
}
__global__ void __launch_bounds__(256) k_chain(int pw, const float* __restrict__ brec) {
    int idx = blockIdx.x * 256 + threadIdx.x;
    int m = idx >> 11, n = idx & (NH_ - 1);
    float v = sinf(g_xin_mn[m][n] + g_G[0][m][n] + brec[n]);
    store_q(pw, 0, m, n, v);
#pragma unroll
    for (int l = 1; l < L_; ++l) {
        v = sinf(v + g_G[l][m][n] + brec[l * NH_ + n]);
        store_q(pw, l, m, n, v);
    }
    g_hTmn[m][n] = v;
}
__global__ void __launch_bounds__(256) k_out_reduce(const float* __restrict__ bout,
                                                    float* __restrict__ out) {
    int idx = blockIdx.x * 256 + threadIdx.x;  // B*NOUT threads, out is [m][n]
    int n = idx & (NOUT_ - 1), m = idx >> 8;
    float v = bout[n];
#pragma unroll
    for (int z = 0; z < 32; ++z) v += g_opart[z][n][m];
    out[idx] = v;
}

// ================= launch =================
extern "C" void kernel_launch(void* const* d_in, const int* in_sizes, int n_in,
                              void* d_out, int out_size) {
    const float* X    = (const float*)d_in[0];
    const float* Winw = (const float*)d_in[1];
    const float* Winb = (const float*)d_in[2];
    const float* Wrw  = (const float*)d_in[3];
    const float* Wrb  = (const float*)d_in[4];
    const float* Wow  = (const float*)d_in[5];
    const float* Wob  = (const float*)d_in[6];
    float* out = (float*)d_out;

    dim3 tb(32, 8);
    k_tr_X   <<<dim3(NIN_ / 32, B_ / 32), tb>>>(X);
    k_tr_Win <<<dim3(NIN_ / 32, NH_ / 32), tb>>>(Winw);
    k_tr_Wout<<<dim3(NH_ / 32, NOUT_ / 32), tb>>>(Wow);
    k_split_W<<<L_ * NH_ * NH_ / 256, 256>>>(Wrw);

    k_proj_gemm  <<<dim3(B_ / BI, NH_ / BJ, 4), 256>>>();
    k_proj_reduce<<<NH_ * B_ / 256, 256>>>(Winb);
    k_tr_xin     <<<dim3(B_ / 32, NH_ / 32), tb>>>();

    k_step0<<<B_ * NH_ / 256, 256>>>(Wrb);   // t = 0 (h starts at zero)

    for (int t = 1; t < T_; ++t) {
        int pw = t & 1;
        k_mma_step<<<dim3(B_ / 128, NH_ / 128, L_), 256>>>(pw ^ 1);
        k_chain   <<<B_ * NH_ / 256, 256>>>(pw, Wrb);
    }

    k_tr_hfin   <<<dim3(NH_ / 32, B_ / 32), tb>>>();
    k_out_gemm  <<<dim3(B_ / BI, NOUT_ / BJ, 32), 256>>>();
    k_out_reduce<<<B_ * NOUT_ / 256, 256>>>(Wob, out);
}

// round 15
// speedup vs baseline: 4.4896x; 4.4896x over previous
#include <cuda_runtime.h>
#include <cuda_bf16.h>
#include <cstdint>
#include <math.h>

// Problem constants (fixed by the dataset's setup_inputs)
#define B_    256
#define NIN_  1024
#define NOUT_ 256
#define NH_   2048
#define L_    4
#define T_    32

// ================= scratch (static __device__ — no allocation) =================
__device__ __align__(128) __nv_bfloat16 g_Whi[L_][NH_][NH_];   // W_rec hi  [l][n][k] 32MB
__device__ __align__(128) __nv_bfloat16 g_Wlo[L_][NH_][NH_];   // W_rec lo  [l][n][k] 32MB
__device__ __align__(128) __nv_bfloat16 g_hhi[2][L_][B_][NH_]; // h hi [m][k]          8MB
__device__ __align__(128) __nv_bfloat16 g_hlo[2][L_][B_][NH_]; // h lo [m][k]          8MB
__device__ float g_G[L_][B_][NH_];        // recurrent GEMM out [l][m][n]   8 MB
__device__ float g_xin_mn[B_][NH_];       // x_in [m][n]                    2 MB
__device__ float g_hTmn[B_][NH_];         // layer L-1 fp32 h [m][n]        2 MB
__device__ float g_hnm[NH_][B_];          // transposed for out proj        2 MB
__device__ float g_Win_T[NIN_][NH_];      // W_in transposed [k][n]         8 MB
__device__ float g_X_T[NIN_][B_];         // X transposed [k][m]            1 MB
__device__ float g_Wout_T[NH_][NOUT_];    // W_out transposed [k][n]        2 MB
__device__ float g_xin[NH_][B_];          // x_in [n][m] (fp32 gemm output) 2 MB
__device__ float g_ppart[4][NH_][B_];     // proj split-K partials          8 MB
__device__ float g_opart[32][NOUT_][B_];  // out  split-K partials          8 MB

// ================= PTX helpers =================
__device__ __forceinline__ unsigned long long fdup(float a) {
    unsigned long long r; unsigned ai = __float_as_uint(a);
    asm("mov.b64 %0, {%1, %1};" : "=l"(r) : "r"(ai));
    return r;
}
__device__ __forceinline__ void fma2(unsigned long long& d, unsigned long long a,
                                     unsigned long long b) {
    asm("fma.rn.f32x2 %0, %1, %2, %0;" : "+l"(d) : "l"(a), "l"(b));
}
__device__ __forceinline__ void cpa16(void* sdst, const void* gsrc) {
    unsigned saddr = (unsigned)__cvta_generic_to_shared(sdst);
    asm volatile("cp.async.cg.shared.global [%0], [%1], 16;\n" :: "r"(saddr), "l"(gsrc));
}
__device__ __forceinline__ void cpa16s(unsigned saddr, const void* gsrc) {
    asm volatile("cp.async.cg.shared.global [%0], [%1], 16;\n" :: "r"(saddr), "l"(gsrc));
}
__device__ __forceinline__ void cpa_commit() { asm volatile("cp.async.commit_group;\n"); }
template <int N_> __device__ __forceinline__ void cpa_wait() {
    asm volatile("cp.async.wait_group %0;\n" :: "n"(N_));
}
__device__ __forceinline__ uint32_t smem_u32(const void* p) {
    uint32_t a;
    asm("{ .reg .u64 t; cvta.to.shared.u64 t, %1; cvt.u32.u64 %0, t; }" : "=r"(a) : "l"(p));
    return a;
}
__device__ __forceinline__ void ldm_x4(uint32_t& r0, uint32_t& r1, uint32_t& r2,
                                       uint32_t& r3, uint32_t addr) {
    asm volatile("ldmatrix.sync.aligned.m8n8.x4.shared.b16 {%0,%1,%2,%3}, [%4];"
                 : "=r"(r0), "=r"(r1), "=r"(r2), "=r"(r3) : "r"(addr));
}
__device__ __forceinline__ void mma_bf16(float* c, const uint32_t* a, uint32_t b0,
                                         uint32_t b1) {
    asm volatile(
        "mma.sync.aligned.m16n8k16.row.col.f32.bf16.bf16.f32 "
        "{%0,%1,%2,%3}, {%4,%5,%6,%7}, {%8,%9}, {%0,%1,%2,%3};"
        : "+f"(c[0]), "+f"(c[1]), "+f"(c[2]), "+f"(c[3])
        : "r"(a[0]), "r"(a[1]), "r"(a[2]), "r"(a[3]), "r"(b0), "r"(b1));
}

// ================= HMMA recurrent GEMM (fused 3-pass per k-chunk) =================
// G[l][m][n] = sum_k h[m][k]*W[l][n][k]; bf16 hi/lo split, single fp32 accum:
//   G = h_hi*w_hi + h_lo*w_hi + h_hi*w_lo   (3 passes, fused per k-chunk)
// Per stage: ONE k-chunk of 64, ALL FOUR tiles (Ahi, Alo, Bhi, Blo) loaded once,
// 3 mma passes run on them -> 32 stages total (vs 192), 1 __syncthreads/stage.
// CTA tile 128x128, 8 warps (warp tile 64x32), double-buffered dynamic smem.
// Smem tile rows: 64 bf16 = 128 B = 8 x 16B chunks; swizzle phys = c ^ (row&7)
// -> ldmatrix 8-row fetches hit all 8 chunk columns = all 32 banks, conflict-free.
#define NSTG   32          // 2048 / 64
#define TILE16 16384       // 128 rows * 128 B
#define STAGE_B (4 * TILE16)
#define MMA_SMEM (2 * STAGE_B)   // 131072

__global__ void __launch_bounds__(256) k_mma_step(int pr) {
    extern __shared__ __align__(128) char smem[];
    const uint32_t sbase = smem_u32(smem);

    const int tid = threadIdx.x;
    const int wid = tid >> 5, lane = tid & 31;
    const int wm = wid & 1, wn = wid >> 1;
    const int m0 = blockIdx.x * 128;
    const int n0 = blockIdx.y * 128;
    const int l  = blockIdx.z;

    // tile sources, all row stride NH_*2 = 4096 bytes
    const char* srcs[4] = {
        (const char*)&g_hhi[pr][l][m0][0],   // 0: A hi
        (const char*)&g_hlo[pr][l][m0][0],   // 1: A lo
        (const char*)&g_Whi[l][n0][0],       // 2: B hi
        (const char*)&g_Wlo[l][n0][0]        // 3: B lo
    };

    auto load_stage = [&](int buf, int st) {
        const uint32_t sb0 = sbase + buf * STAGE_B;
        const size_t ko = (size_t)st * 128;  // 64 bf16 = 128 B along K
#pragma unroll
        for (int t = 0; t < 4; ++t) {
            const char* src = srcs[t];
            const uint32_t db = sb0 + t * TILE16;
#pragma unroll
            for (int j = 0; j < 4; ++j) {
                int ch = tid + 256 * j;         // 0..1023
                int row = ch >> 3, c = ch & 7;
                uint32_t sw = ((uint32_t)(c ^ (row & 7))) << 4;
                cpa16s(db + row * 128 + sw, src + (size_t)row * 4096 + ko + c * 16);
            }
        }
        cpa_commit();
    };

    float acc[4][4][4];
#pragma unroll
    for (int a = 0; a < 4; ++a)
#pragma unroll
        for (int b = 0; b < 4; ++b)
#pragma unroll
            for (int r = 0; r < 4; ++r) acc[a][b][r] = 0.f;

    // per-lane ldmatrix addressing; swizzle term = row & 7 = lane & 7 (base rows
    // and mf*16 / nf2*16 / wm*64 / wn*32 offsets all preserve row mod 8)
    const uint32_t swz  = lane & 7;
    const uint32_t aRow = (uint32_t)(wm * 64 + (lane & 15));                     // + mf*16
    const uint32_t aHalf = (lane >> 4) & 1;
    const uint32_t bRow = (uint32_t)(wn * 32 + (lane & 7) + ((lane >> 4) << 3)); // + nf2*16
    const uint32_t bHalf = (lane >> 3) & 1;

    load_stage(0, 0);
    for (int s = 0; s < NSTG; ++s) {
        const int b = s & 1;
        cpa_wait<0>();          // stage s resident
        __syncthreads();        // visible to all; all warps done with buf b^1
        if (s + 1 < NSTG) load_stage(b ^ 1, s + 1);   // overlaps compute below

        const uint32_t st0 = sbase + b * STAGE_B;
#pragma unroll
        for (int p = 0; p < 3; ++p) {   // (Ahi,Bhi), (Alo,Bhi), (Ahi,Blo)
            const uint32_t sA = st0 + ((p == 1) ? 1 : 0) * TILE16;
            const uint32_t sB = st0 + ((p == 2) ? 3 : 2) * TILE16;
#pragma unroll
            for (int ks = 0; ks < 4; ++ks) {
                uint32_t af[4][4];
#pragma unroll
                for (int mf = 0; mf < 4; ++mf) {
                    uint32_t addr = sA + (aRow + mf * 16) * 128 +
                                    (((2 * ks + aHalf) ^ swz) << 4);
                    ldm_x4(af[mf][0], af[mf][1], af[mf][2], af[mf][3], addr);
                }
                uint32_t bf[2][4];
#pragma unroll
                for (int nf2 = 0; nf2 < 2; ++nf2) {
                    uint32_t addr = sB + (bRow + nf2 * 16) * 128 +
                                    (((2 * ks + bHalf) ^ swz) << 4);
                    ldm_x4(bf[nf2][0], bf[nf2][1], bf[nf2][2], bf[nf2][3], addr);
                }
#pragma unroll
                for (int mf = 0; mf < 4; ++mf)
#pragma unroll
                    for (int nf = 0; nf < 4; ++nf)
                        mma_bf16(acc[mf][nf], af[mf], bf[nf >> 1][(nf & 1) * 2],
                                 bf[nf >> 1][(nf & 1) * 2 + 1]);
            }
        }
    }

    // epilogue: c-frag m16n8 -> rows (lane>>2, +8), cols 2*(lane&3)
    const int r = lane >> 2, cp = lane & 3;
#pragma unroll
    for (int mf = 0; mf < 4; ++mf)
#pragma unroll
        for (int nf = 0; nf < 4; ++nf) {
            float* dst = &g_G[l][m0 + wm * 64 + mf * 16 + r][n0 + wn * 32 + nf * 8 + cp * 2];
            *(float2*)dst = make_float2(acc[mf][nf][0], acc[mf][nf][1]);
            *(float2*)(dst + 8 * NH_) = make_float2(acc[mf][nf][2], acc[mf][nf][3]);
        }
}

// ================= weight split fp32 -> bf16 hi/lo =================
__global__ void __launch_bounds__(256) k_split_W(const float* __restrict__ w) {
    size_t idx = (size_t)blockIdx.x * 256 + threadIdx.x;  // L*NH*NH threads
    float v = w[idx];
    __nv_bfloat16 hi = __float2bfloat16_rn(v);
    float lo = v - __bfloat162float(hi);
    ((__nv_bfloat16*)g_Whi)[idx] = hi;
    ((__nv_bfloat16*)g_Wlo)[idx] = __float2bfloat16_rn(lo);
}

// ================= transpose (fp32 paths) =================
__device__ __forceinline__ void tr_body(const float* __restrict__ src,
                                        float* __restrict__ dst, int R, int C) {
    __shared__ float t[32][33];
    int c0 = blockIdx.x * 32, r0 = blockIdx.y * 32;
    int tx = threadIdx.x, ty = threadIdx.y;  // 32 x 8
#pragma unroll
    for (int i = 0; i < 32; i += 8)
        t[ty + i][tx] = src[(size_t)(r0 + ty + i) * C + c0 + tx];
    __syncthreads();
#pragma unroll
    for (int i = 0; i < 32; i += 8)
        dst[(size_t)(c0 + ty + i) * R + r0 + tx] = t[tx][ty + i];
}
__global__ void __launch_bounds__(256) k_tr_X(const float* __restrict__ s) {
    tr_body(s, &g_X_T[0][0], B_, NIN_);
}
__global__ void __launch_bounds__(256) k_tr_Win(const float* __restrict__ s) {
    tr_body(s, &g_Win_T[0][0], NH_, NIN_);
}
__global__ void __launch_bounds__(256) k_tr_Wout(const float* __restrict__ s) {
    tr_body(s, &g_Wout_T[0][0], NOUT_, NH_);
}
__global__ void __launch_bounds__(256) k_tr_xin() {    // [n][m] -> [m][n]
    tr_body(&g_xin[0][0], &g_xin_mn[0][0], NH_, B_);
}
__global__ void __launch_bounds__(256) k_tr_hfin() {   // [m][n] -> [n][m]
    tr_body(&g_hTmn[0][0], &g_hnm[0][0], B_, NH_);
}

// ================= fp32 SIMT GEMM (proj / out only) =================
#define BI 128
#define BJ 128
#define BK 16
__device__ __forceinline__ void gemm_tile(const float* __restrict__ A,
                                          const float* __restrict__ Bp,
                                          float* __restrict__ C,
                                          int lda, int ldb, int ldc,
                                          int k0, int klen) {
    __shared__ __align__(16) float As[2][BK][BI];
    __shared__ __align__(16) float Bs[2][BK][BJ];
    const int tid = threadIdx.x;
    const int tx = tid & 15;
    const int ty = tid >> 4;
    const int i0 = blockIdx.x * BI;
    const int j0 = blockIdx.y * BJ;
    const int lk = tid >> 5;
    const int li = (tid & 31) * 4;

#define LOAD_STAGE(buf, kbase)                                                        \
    do {                                                                              \
        cpa16(&As[buf][lk][li],     A  + (size_t)((kbase) + lk)     * lda + i0 + li); \
        cpa16(&As[buf][lk + 8][li], A  + (size_t)((kbase) + lk + 8) * lda + i0 + li); \
        cpa16(&Bs[buf][lk][li],     Bp + (size_t)((kbase) + lk)     * ldb + j0 + li); \
        cpa16(&Bs[buf][lk + 8][li], Bp + (size_t)((kbase) + lk + 8) * ldb + j0 + li); \
        cpa_commit();                                                                 \
    } while (0)

    unsigned long long acc[8][4];
#pragma unroll
    for (int ii = 0; ii < 8; ++ii)
#pragma unroll
        for (int jj = 0; jj < 4; ++jj) acc[ii][jj] = 0ull;

    const int nst = klen / BK;
    LOAD_STAGE(0, k0);
    for (int s = 0; s < nst; ++s) {
        const int cur = s & 1;
        if (s + 1 < nst) { LOAD_STAGE(cur ^ 1, k0 + (s + 1) * BK); cpa_wait<1>(); }
        else             { cpa_wait<0>(); }
        __syncthreads();
#pragma unroll
        for (int kk = 0; kk < BK; ++kk) {
            float4 alo = *(const float4*)&As[cur][kk][tx * 8];
            float4 ahi = *(const float4*)&As[cur][kk][tx * 8 + 4];
            ulonglong2 bA = *(const ulonglong2*)&Bs[cur][kk][ty * 8];
            ulonglong2 bB = *(const ulonglong2*)&Bs[cur][kk][ty * 8 + 4];
            unsigned long long bb0 = bA.x, bb1 = bA.y, bb2 = bB.x, bb3 = bB.y;
            float av[8] = {alo.x, alo.y, alo.z, alo.w, ahi.x, ahi.y, ahi.z, ahi.w};
#pragma unroll
            for (int ii = 0; ii < 8; ++ii) {
                unsigned long long ad = fdup(av[ii]);
                fma2(acc[ii][0], ad, bb0);
                fma2(acc[ii][1], ad, bb1);
                fma2(acc[ii][2], ad, bb2);
                fma2(acc[ii][3], ad, bb3);
            }
        }
        __syncthreads();
    }
#undef LOAD_STAGE
#pragma unroll
    for (int jj = 0; jj < 8; ++jj) {
        float v[8];
#pragma unroll
        for (int ii = 0; ii < 8; ++ii) {
            union { unsigned long long u; float2 f; } cv;
            cv.u = acc[ii][jj >> 1];
            v[ii] = (jj & 1) ? cv.f.y : cv.f.x;
        }
        float* row = C + (size_t)(j0 + ty * 8 + jj) * ldc + i0 + tx * 8;
        *(float4*)row       = make_float4(v[0], v[1], v[2], v[3]);
        *(float4*)(row + 4) = make_float4(v[4], v[5], v[6], v[7]);
    }
}
__global__ void __launch_bounds__(256) k_proj_gemm() {
    int z = blockIdx.z;
    gemm_tile(&g_X_T[0][0], &g_Win_T[0][0], &g_ppart[z][0][0], B_, NH_, B_,
              z * (NIN_ / 4), NIN_ / 4);
}
__global__ void __launch_bounds__(256) k_out_gemm() {
    int z = blockIdx.z;
    gemm_tile(&g_hnm[0][0], &g_Wout_T[0][0], &g_opart[z][0][0], B_, NOUT_, B_,
              z * (NH_ / 32), NH_ / 32);
}

// ================= elementwise =================
__global__ void __launch_bounds__(256) k_proj_reduce(const float* __restrict__ bin) {
    int idx = blockIdx.x * 256 + threadIdx.x;  // NH*B threads, [n][m]
    int n = idx >> 8, m = idx & (B_ - 1);
    float v = bin[n];
#pragma unroll
    for (int z = 0; z < 4; ++z) v += g_ppart[z][n][m];
    g_xin[n][m] = v;
}
__device__ __forceinline__ void store_split(int pw, int l, int m, int n, float v) {
    __nv_bfloat16 hi = __float2bfloat16_rn(v);
    g_hhi[pw][l][m][n] = hi;
    g_hlo[pw][l][m][n] = __float2bfloat16_rn(v - __bfloat162float(hi));
}
__global__ void __launch_bounds__(256) k_step0(const float* __restrict__ brec) {
    int idx = blockIdx.x * 256 + threadIdx.x;  // B*NH threads, [m][n]
    int m = idx >> 11, n = idx & (NH_ - 1);
    float v = sinf(g_xin_mn[m][n] + brec[n]);
    store_split(0, 0, m, n, v);
#pragma unroll
    for (int l = 1; l < L_; ++l) {
        v = sinf(v + brec[l * NH_ + n]);
        store_split(0, l, m, n, v);
    }
    g_hTmn[m][n] = v;
}
__global__ void __launch_bounds__(256) k_chain(int pw, const float* __restrict__ brec) {
    int idx = blockIdx.x * 256 + threadIdx.x;
    int m = idx >> 11, n = idx & (NH_ - 1);
    float v = sinf(g_xin_mn[m][n] + g_G[0][m][n] + brec[n]);
    store_split(pw, 0, m, n, v);
#pragma unroll
    for (int l = 1; l < L_; ++l) {
        v = sinf(v + g_G[l][m][n] + brec[l * NH_ + n]);
        store_split(pw, l, m, n, v);
    }
    g_hTmn[m][n] = v;
}
__global__ void __launch_bounds__(256) k_out_reduce(const float* __restrict__ bout,
                                                    float* __restrict__ out) {
    int idx = blockIdx.x * 256 + threadIdx.x;  // B*NOUT threads, out is [m][n]
    int n = idx & (NOUT_ - 1), m = idx >> 8;
    float v = bout[n];
#pragma unroll
    for (int z = 0; z < 32; ++z) v += g_opart[z][n][m];
    out[idx] = v;
}

// ================= launch =================
extern "C" void kernel_launch(void* const* d_in, const int* in_sizes, int n_in,
                              void* d_out, int out_size) {
    const float* X    = (const float*)d_in[0];
    const float* Winw = (const float*)d_in[1];
    const float* Winb = (const float*)d_in[2];
    const float* Wrw  = (const float*)d_in[3];
    const float* Wrb  = (const float*)d_in[4];
    const float* Wow  = (const float*)d_in[5];
    const float* Wob  = (const float*)d_in[6];
    float* out = (float*)d_out;

    cudaFuncSetAttribute(k_mma_step, cudaFuncAttributeMaxDynamicSharedMemorySize,
                         MMA_SMEM);

    dim3 tb(32, 8);
    k_tr_X   <<<dim3(NIN_ / 32, B_ / 32), tb>>>(X);
    k_tr_Win <<<dim3(NIN_ / 32, NH_ / 32), tb>>>(Winw);
    k_tr_Wout<<<dim3(NH_ / 32, NOUT_ / 32), tb>>>(Wow);
    k_split_W<<<L_ * NH_ * NH_ / 256, 256>>>(Wrw);

    k_proj_gemm  <<<dim3(B_ / BI, NH_ / BJ, 4), 256>>>();
    k_proj_reduce<<<NH_ * B_ / 256, 256>>>(Winb);
    k_tr_xin     <<<dim3(B_ / 32, NH_ / 32), tb>>>();

    k_step0<<<B_ * NH_ / 256, 256>>>(Wrb);   // t = 0 (h starts at zero)

    for (int t = 1; t < T_; ++t) {
        int pw = t & 1;
        k_mma_step<<<dim3(B_ / 128, NH_ / 128, L_), 256, MMA_SMEM>>>(pw ^ 1);
        k_chain   <<<B_ * NH_ / 256, 256>>>(pw, Wrb);
    }

    k_tr_hfin   <<<dim3(NH_ / 32, B_ / 32), tb>>>();
    k_out_gemm  <<<dim3(B_ / BI, NOUT_ / BJ, 32), 256>>>();
    k_out_reduce<<<B_ * NOUT_ / 256, 256>>>(Wob, out);
}